// round 13
// baseline (speedup 1.0000x reference)
#include <cuda_runtime.h>

#define TPB    64     // 2 warps; each warp owns 64 output columns
#define WPC    64
#define CBLK   128
#define TYO    32
#define WIN    11
#define HALO   5
#define RING   12     // 12-slot ring enables paired-row emit
#define IMG_H  512
#define IMG_W  512
#define TLAST  42     // steps t = 0..41
#define NSTEP  48     // edge path: 4 * RING
#define NPAIR  38

#define C1F  1.0e-4f
#define C2F  9.0e-4f
#define EPSF 1.0e-8f

typedef unsigned long long u64;

__device__ double       g_ssim_acc;
__device__ unsigned int g_ssim_cnt;

__device__ __forceinline__ u64 pk2(float lo, float hi) {
    u64 r; asm("mov.b64 %0,{%1,%2};" : "=l"(r) : "f"(lo), "f"(hi)); return r;
}
__device__ __forceinline__ void upk2(u64 v, float& lo, float& hi) {
    asm("mov.b64 {%0,%1},%2;" : "=f"(lo), "=f"(hi) : "l"(v));
}
__device__ __forceinline__ u64 fma2(u64 a, u64 b, u64 c) {
    u64 d; asm("fma.rn.f32x2 %0,%1,%2,%3;" : "=l"(d) : "l"(a), "l"(b), "l"(c)); return d;
}
__device__ __forceinline__ u64 mul2(u64 a, u64 b) {
    u64 d; asm("mul.rn.f32x2 %0,%1,%2;" : "=l"(d) : "l"(a), "l"(b)); return d;
}
__device__ __forceinline__ u64 add2(u64 a, u64 b) {
    u64 d; asm("add.rn.f32x2 %0,%1,%2;" : "=l"(d) : "l"(a), "l"(b)); return d;
}
__device__ __forceinline__ u64 neg2(u64 a) { return a ^ 0x8000000080000000ull; }

__global__ void __launch_bounds__(TPB, 9) ssim_main_kernel(
    const float* __restrict__ x,
    const float* __restrict__ y,
    const float* __restrict__ w,
    float* __restrict__ out,
    double inv_total)
{
    __shared__ float sg[WIN];
    __shared__ __align__(16) float4 sbuf[2][2][40];
    __shared__ u64 ringPP[2][RING][32];
    __shared__ u64 ringMM[2][RING][32];
    __shared__ float swp[TPB / 32];

    const int tid  = threadIdx.x;
    const int lane = tid & 31;
    const int wid  = tid >> 5;

    if (tid < WIN) {
        float s = 0.f;
        #pragma unroll
        for (int j = 0; j < WIN; ++j) s += __ldg(w + tid * WIN + j);
        sg[tid] = s;
    }
    __syncthreads();

    u64 g2[6];
    #pragma unroll
    for (int d = 0; d < 6; ++d) { float gd = sg[d]; g2[d] = pk2(gd, gd); }

    const u64 C1P  = pk2(C1F, C1F);
    const u64 C2P  = pk2(C2F, C2F);
    const u64 EPSP = pk2(EPSF, EPSF);
    const u64 HLF  = pk2(0.5f, 0.5f);

    const int c0 = blockIdx.x * CBLK;
    const int r0 = blockIdx.y * TYO;
    const long img_off = (long)blockIdx.z * (IMG_H * IMG_W);
    const float* xi = x + img_off;
    const float* yi = y + img_off;

    const int cw = c0 + WPC * wid;
    const int cb = cw - 6;

    const int  col1 = cb + 2 * lane;
    const int  col2 = col1 + 64;
    const bool c1ok = (col1 >= 0) && (col1 < IMG_W);
    const bool c2ok = (lane < NPAIR - 32) && (col2 < IMG_W);

    // rP/rM rings in registers (12 slots); rPP/rMM rings in SMEM.
    u64 rP[RING], rM[RING];
    #pragma unroll
    for (int s = 0; s < RING; ++s) { rP[s]=0; rM[s]=0; }
    u64* myPP = &ringPP[wid][0][lane];   // slot stride = 32 u64
    u64* myMM = &ringMM[wid][0][lane];

    float lsum0 = 0.f, lsum1 = 0.f;

    // ---- shared compute macros -------------------------------------------
    #define VPAIR_R(RA, RB, RNG, JJ)                                           \
    {                                                                          \
        RA = mul2(g2[5], RNG[((JJ) + 6) % RING]);                              \
        RB = mul2(g2[5], RNG[((JJ) + 7) % RING]);                              \
        _Pragma("unroll")                                                      \
        for (int d = 0; d < 5; ++d) {                                          \
            RA = fma2(g2[d], add2(RNG[((JJ) + 1 + d) % RING],                  \
                                  RNG[((JJ) + 11 - d) % RING]), RA);           \
            RB = fma2(g2[d], add2(RNG[((JJ) + 2 + d) % RING],                  \
                                  RNG[((JJ) + 12 - d) % RING]), RB);           \
        }                                                                      \
    }
    #define VPAIR_S(RA, RB, BASE, JJ)                                          \
    {                                                                          \
        u64 v_[RING];                                                          \
        _Pragma("unroll")                                                      \
        for (int s = 0; s < RING; ++s) v_[s] = (BASE)[s * 32];                 \
        RA = mul2(g2[5], v_[((JJ) + 6) % RING]);                               \
        RB = mul2(g2[5], v_[((JJ) + 7) % RING]);                               \
        _Pragma("unroll")                                                      \
        for (int d = 0; d < 5; ++d) {                                          \
            RA = fma2(g2[d], add2(v_[((JJ) + 1 + d) % RING],                   \
                                  v_[((JJ) + 11 - d) % RING]), RA);            \
            RB = fma2(g2[d], add2(v_[((JJ) + 2 + d) % RING],                   \
                                  v_[((JJ) + 12 - d) % RING]), RB);            \
        }                                                                      \
    }
    #define SSIM_EMIT(MP, MM_, EPP, EMM)                                       \
    {                                                                          \
        const u64 a_  = mul2(MP, MP);                                          \
        const u64 b_  = mul2(MM_, MM_);                                        \
        const u64 A_  = mul2(HLF, add2(a_, b_));                               \
        const u64 P2_ = mul2(HLF, add2(a_, neg2(b_)));                         \
        const u64 S_  = mul2(HLF, add2(EPP, EMM));                             \
        const u64 E2_ = mul2(HLF, add2(EPP, neg2(EMM)));                       \
        const u64 n1_ = add2(P2_, C1P);                                        \
        const u64 n2_ = add2(add2(E2_, C2P), neg2(P2_));                       \
        const u64 d1_ = add2(A_, C1P);                                         \
        const u64 d2_ = add2(add2(S_, C2P), neg2(A_));                         \
        const u64 nu_ = mul2(n1_, n2_);                                        \
        const u64 de_ = fma2(d1_, d2_, EPSP);                                  \
        float n0_, n1s_, dd0_, dd1_;                                           \
        upk2(nu_, n0_, n1s_);                                                  \
        upk2(de_, dd0_, dd1_);                                                 \
        float v0_ = __fdividef(n0_,  dd0_);                                    \
        float v1_ = __fdividef(n1s_, dd1_);                                    \
        lsum0 += fminf(fmaxf(v0_, 0.f), 1.f);                                  \
        lsum1 += fminf(fmaxf(v1_, 0.f), 1.f);                                  \
    }
    #define HPAIR(D, PA, MA, PB, MB)                                           \
    {                                                                          \
        hP  = fma2(g2[D], add2(PA, PB), hP);                                   \
        hM  = fma2(g2[D], add2(MA, MB), hM);                                   \
        hPP = fma2(g2[D], fma2(PA, PA, mul2(PB, PB)), hPP);                    \
        hMM = fma2(g2[D], fma2(MA, MA, mul2(MB, MB)), hMM);                    \
    }
    // Stage, hconv, ring write, optional paired emit.  EM: 1 = emit rows.
    #define STEP_CORE(JJ, EM)                                                  \
    {                                                                          \
        float4* buf = &sbuf[wid][(JJ) & 1][0];                                 \
        {                                                                      \
            float4 s1;                                                         \
            s1.x = f1x.x + f1y.x;  s1.y = f1x.y + f1y.y;                       \
            s1.z = f1x.x - f1y.x;  s1.w = f1x.y - f1y.y;                       \
            buf[lane] = s1;                                                    \
            if (lane < NPAIR - 32) {                                           \
                float4 s2;                                                     \
                s2.x = f2x.x + f2y.x;  s2.y = f2x.y + f2y.y;                   \
                s2.z = f2x.x - f2y.x;  s2.w = f2x.y - f2y.y;                   \
                buf[32 + lane] = s2;                                           \
            }                                                                  \
        }                                                                      \
        PREFETCH_NEXT                                                          \
        __syncwarp();                                                          \
        float4 f[7];                                                           \
        _Pragma("unroll")                                                      \
        for (int j = 0; j < 7; ++j) f[j] = buf[lane + j];                      \
        const u64 P0 = pk2(f[0].y, f[1].x), M0 = pk2(f[0].w, f[1].z);          \
        const u64 P1 = pk2(f[1].x, f[1].y), M1 = pk2(f[1].z, f[1].w);          \
        const u64 P2 = pk2(f[1].y, f[2].x), M2 = pk2(f[1].w, f[2].z);          \
        const u64 P3 = pk2(f[2].x, f[2].y), M3 = pk2(f[2].z, f[2].w);          \
        const u64 P4 = pk2(f[2].y, f[3].x), M4 = pk2(f[2].w, f[3].z);          \
        const u64 P5 = pk2(f[3].x, f[3].y), M5 = pk2(f[3].z, f[3].w);          \
        const u64 P6 = pk2(f[3].y, f[4].x), M6 = pk2(f[3].w, f[4].z);          \
        const u64 P7 = pk2(f[4].x, f[4].y), M7 = pk2(f[4].z, f[4].w);          \
        const u64 P8 = pk2(f[4].y, f[5].x), M8 = pk2(f[4].w, f[5].z);          \
        const u64 P9 = pk2(f[5].x, f[5].y), M9 = pk2(f[5].z, f[5].w);          \
        const u64 PA = pk2(f[5].y, f[6].x), MA = pk2(f[5].w, f[6].z);          \
        u64 hP = mul2(g2[5], P5);                                              \
        u64 hM = mul2(g2[5], M5);                                              \
        u64 hPP = mul2(hP, P5);                                                \
        u64 hMM = mul2(hM, M5);                                                \
        HPAIR(0, P0, M0, PA, MA)                                               \
        HPAIR(1, P1, M1, P9, M9)                                               \
        HPAIR(2, P2, M2, P8, M8)                                               \
        HPAIR(3, P3, M3, P7, M7)                                               \
        HPAIR(4, P4, M4, P6, M6)                                               \
        rP[(JJ) % RING] = hP;  rM[(JJ) % RING] = hM;                           \
        myPP[((JJ) % RING) * 32] = hPP;                                        \
        myMM[((JJ) % RING) * 32] = hMM;                                        \
        if (EM) {                                                              \
            u64 mpA, mpB, mmA, mmB, eppA, eppB, emmA, emmB;                    \
            VPAIR_R(mpA, mpB, rP, (JJ))                                        \
            VPAIR_R(mmA, mmB, rM, (JJ))                                        \
            VPAIR_S(eppA, eppB, myPP, (JJ))                                    \
            VPAIR_S(emmA, emmB, myMM, (JJ))                                    \
            SSIM_EMIT(mpA, mmA, eppA, emmA)                                    \
            SSIM_EMIT(mpB, mmB, eppB, emmB)                                    \
        }                                                                      \
    }

    if (r0 >= HALO && r0 + TYO + HALO + 1 <= IMG_H) {
        // ---------------- interior path: no row checks, running pointers ----
        const float* xr = xi + (long)(r0 - HALO) * IMG_W;
        const float* yr = yi + (long)(r0 - HALO) * IMG_W;

        float2 f1x, f1y, f2x, f2y;
        const float2 z = make_float2(0.f, 0.f);
        f1x = c1ok ? __ldg((const float2*)(xr + col1)) : z;
        f1y = c1ok ? __ldg((const float2*)(yr + col1)) : z;
        f2x = c2ok ? __ldg((const float2*)(xr + col2)) : z;
        f2y = c2ok ? __ldg((const float2*)(yr + col2)) : z;
        xr += IMG_W; yr += IMG_W;

        #define PREFETCH_NEXT                                                  \
        {                                                                      \
            f1x = c1ok ? __ldg((const float2*)(xr + col1)) : z;                \
            f1y = c1ok ? __ldg((const float2*)(yr + col1)) : z;                \
            f2x = c2ok ? __ldg((const float2*)(xr + col2)) : z;                \
            f2y = c2ok ? __ldg((const float2*)(yr + col2)) : z;                \
            xr += IMG_W; yr += IMG_W;                                          \
        }

        // Steps 0..11 (emit only at step 11).
        STEP_CORE(0,0)  STEP_CORE(1,0)  STEP_CORE(2,0)  STEP_CORE(3,0)
        STEP_CORE(4,0)  STEP_CORE(5,0)  STEP_CORE(6,0)  STEP_CORE(7,0)
        STEP_CORE(8,0)  STEP_CORE(9,0)  STEP_CORE(10,0) STEP_CORE(11,1)
        // Steps 12..35 (two identical blocks; nothing depends on t).
        #pragma unroll 1
        for (int it = 0; it < 2; ++it) {
            STEP_CORE(0,0)  STEP_CORE(1,1)  STEP_CORE(2,0)  STEP_CORE(3,1)
            STEP_CORE(4,0)  STEP_CORE(5,1)  STEP_CORE(6,0)  STEP_CORE(7,1)
            STEP_CORE(8,0)  STEP_CORE(9,1)  STEP_CORE(10,0) STEP_CORE(11,1)
        }
        // Tail: steps 36..41.
        STEP_CORE(0,0)  STEP_CORE(1,1)  STEP_CORE(2,0)  STEP_CORE(3,1)
        STEP_CORE(4,0)  STEP_CORE(5,1)
        #undef PREFETCH_NEXT
    } else {
        // ---------------- edge path: full row checks ------------------------
        #pragma unroll
        for (int s = 0; s < RING; ++s) { myPP[s * 32] = 0; myMM[s * 32] = 0; }

        float2 f1x, f1y, f2x, f2y;
        {
            const int ir = r0 - HALO;
            const bool rv = (ir >= 0);
            const float* xr = xi + (long)ir * IMG_W;
            const float* yr = yi + (long)ir * IMG_W;
            const float2 z = make_float2(0.f, 0.f);
            f1x = (rv && c1ok) ? __ldg((const float2*)(xr + col1)) : z;
            f1y = (rv && c1ok) ? __ldg((const float2*)(yr + col1)) : z;
            f2x = (rv && c2ok) ? __ldg((const float2*)(xr + col2)) : z;
            f2y = (rv && c2ok) ? __ldg((const float2*)(yr + col2)) : z;
        }

        #define PREFETCH_NEXT                                                  \
        {                                                                      \
            const int irn = r0 - HALO + t + 1;                                 \
            const bool rv = (irn >= 0) && (irn < IMG_H);                       \
            const float* xr = xi + (long)irn * IMG_W;                          \
            const float* yr = yi + (long)irn * IMG_W;                          \
            const float2 z = make_float2(0.f, 0.f);                            \
            f1x = (rv && c1ok) ? __ldg((const float2*)(xr + col1)) : z;        \
            f1y = (rv && c1ok) ? __ldg((const float2*)(yr + col1)) : z;        \
            f2x = (rv && c2ok) ? __ldg((const float2*)(xr + col2)) : z;        \
            f2y = (rv && c2ok) ? __ldg((const float2*)(yr + col2)) : z;        \
        }
        #define STEP_EDGE(JJ)                                                  \
        if (tbase + (JJ) < TLAST) {                                            \
            const int t = tbase + (JJ);                                        \
            STEP_CORE(JJ, (((JJ) & 1) && t >= WIN))                            \
        }

        #pragma unroll 1
        for (int tbase = 0; tbase < NSTEP; tbase += RING) {
            STEP_EDGE(0)  STEP_EDGE(1)  STEP_EDGE(2)  STEP_EDGE(3)
            STEP_EDGE(4)  STEP_EDGE(5)  STEP_EDGE(6)  STEP_EDGE(7)
            STEP_EDGE(8)  STEP_EDGE(9)  STEP_EDGE(10) STEP_EDGE(11)
        }
        #undef STEP_EDGE
        #undef PREFETCH_NEXT
    }

    #undef STEP_CORE
    #undef HPAIR
    #undef SSIM_EMIT
    #undef VPAIR_R
    #undef VPAIR_S

    float ls = lsum0 + lsum1;
    #pragma unroll
    for (int o = 16; o > 0; o >>= 1)
        ls += __shfl_down_sync(0xFFFFFFFFu, ls, o);
    if (lane == 0) swp[wid] = ls;
    __syncthreads();

    if (tid == 0) {
        float bs = swp[0] + swp[1];
        atomicAdd(&g_ssim_acc, (double)bs);
        __threadfence();
        const unsigned nb = gridDim.x * gridDim.y * gridDim.z;
        const unsigned prev = atomicAdd(&g_ssim_cnt, 1u);
        if (prev == nb - 1u) {
            double acc = atomicAdd(&g_ssim_acc, 0.0);
            out[0] = (float)(acc * inv_total);
            g_ssim_acc = 0.0;
            g_ssim_cnt = 0u;
            __threadfence();
        }
    }
}

extern "C" void kernel_launch(void* const* d_in, const int* in_sizes, int n_in,
                              void* d_out, int out_size) {
    const float* x = (const float*)d_in[0];
    const float* y = (const float*)d_in[1];
    const float* w = (const float*)d_in[2];
    float* out = (float*)d_out;

    const long total = (long)in_sizes[0];
    const int nimg = (int)(total / (IMG_H * IMG_W));

    dim3 grid(IMG_W / CBLK, IMG_H / TYO, nimg);
    ssim_main_kernel<<<grid, TPB>>>(x, y, w, out, 1.0 / (double)total);
}

// round 15
// speedup vs baseline: 1.1055x; 1.1055x over previous
#include <cuda_runtime.h>

#define TPB    64     // 2 warps; each warp owns 64 output columns
#define WPC    64
#define CBLK   128
#define TYO    32
#define WIN    11
#define HALO   5
#define RING   12     // 12-slot ring enables paired-row emit
#define IMG_H  512
#define IMG_W  512
#define TLAST  42     // steps t = 0..41
#define NSTEP  48     // edge path: 4 * RING
#define NPAIR  38

#define C1F  1.0e-4f
#define C2F  9.0e-4f
#define EPSF 1.0e-8f

typedef unsigned long long u64;

__device__ double       g_ssim_acc;
__device__ unsigned int g_ssim_cnt;

__device__ __forceinline__ u64 pk2(float lo, float hi) {
    u64 r; asm("mov.b64 %0,{%1,%2};" : "=l"(r) : "f"(lo), "f"(hi)); return r;
}
__device__ __forceinline__ void upk2(u64 v, float& lo, float& hi) {
    asm("mov.b64 {%0,%1},%2;" : "=f"(lo), "=f"(hi) : "l"(v));
}
__device__ __forceinline__ u64 fma2(u64 a, u64 b, u64 c) {
    u64 d; asm("fma.rn.f32x2 %0,%1,%2,%3;" : "=l"(d) : "l"(a), "l"(b), "l"(c)); return d;
}
__device__ __forceinline__ u64 mul2(u64 a, u64 b) {
    u64 d; asm("mul.rn.f32x2 %0,%1,%2;" : "=l"(d) : "l"(a), "l"(b)); return d;
}
__device__ __forceinline__ u64 add2(u64 a, u64 b) {
    u64 d; asm("add.rn.f32x2 %0,%1,%2;" : "=l"(d) : "l"(a), "l"(b)); return d;
}
__device__ __forceinline__ u64 neg2(u64 a) { return a ^ 0x8000000080000000ull; }

__global__ void __launch_bounds__(TPB, 8) ssim_main_kernel(
    const float* __restrict__ x,
    const float* __restrict__ y,
    const float* __restrict__ w,
    float* __restrict__ out,
    double inv_total)
{
    __shared__ float sg[WIN];
    __shared__ __align__(16) float4 sbuf[2][2][40];
    __shared__ u64 ringPP[2][RING][32];
    __shared__ u64 ringMM[2][RING][32];
    __shared__ float swp[TPB / 32];

    const int tid  = threadIdx.x;
    const int lane = tid & 31;
    const int wid  = tid >> 5;

    if (tid < WIN) {
        float s = 0.f;
        #pragma unroll
        for (int j = 0; j < WIN; ++j) s += __ldg(w + tid * WIN + j);
        sg[tid] = s;
    }
    __syncthreads();

    u64 g2[6];
    #pragma unroll
    for (int d = 0; d < 6; ++d) { float gd = sg[d]; g2[d] = pk2(gd, gd); }

    const u64 C1P  = pk2(C1F, C1F);
    const u64 C2P  = pk2(C2F, C2F);
    const u64 EPSP = pk2(EPSF, EPSF);
    const u64 HLF  = pk2(0.5f, 0.5f);

    const int c0 = blockIdx.x * CBLK;
    const int r0 = blockIdx.y * TYO;
    const long img_off = (long)blockIdx.z * (IMG_H * IMG_W);
    const float* xi = x + img_off;
    const float* yi = y + img_off;

    const int cw = c0 + WPC * wid;
    const int cb = cw - 6;

    const int  col1 = cb + 2 * lane;
    const int  col2 = col1 + 64;
    const bool c1ok = (col1 >= 0) && (col1 < IMG_W);
    const bool c2ok = (lane < NPAIR - 32) && (col2 < IMG_W);

    // rP/rM rings in registers (12 slots); rPP/rMM rings in SMEM.
    u64 rP[RING], rM[RING];
    #pragma unroll
    for (int s = 0; s < RING; ++s) { rP[s]=0; rM[s]=0; }
    u64* myPP = &ringPP[wid][0][lane];   // slot stride = 32 u64
    u64* myMM = &ringMM[wid][0][lane];

    float lsum0 = 0.f, lsum1 = 0.f;

    // ---- shared compute macros -------------------------------------------
    #define VPAIR_R(RA, RB, RNG, JJ)                                           \
    {                                                                          \
        RA = mul2(g2[5], RNG[((JJ) + 6) % RING]);                              \
        RB = mul2(g2[5], RNG[((JJ) + 7) % RING]);                              \
        _Pragma("unroll")                                                      \
        for (int d = 0; d < 5; ++d) {                                          \
            RA = fma2(g2[d], add2(RNG[((JJ) + 1 + d) % RING],                  \
                                  RNG[((JJ) + 11 - d) % RING]), RA);           \
            RB = fma2(g2[d], add2(RNG[((JJ) + 2 + d) % RING],                  \
                                  RNG[((JJ) + 12 - d) % RING]), RB);           \
        }                                                                      \
    }
    #define VPAIR_S(RA, RB, BASE, JJ)                                          \
    {                                                                          \
        u64 v_[RING];                                                          \
        _Pragma("unroll")                                                      \
        for (int s = 0; s < RING; ++s) v_[s] = (BASE)[s * 32];                 \
        RA = mul2(g2[5], v_[((JJ) + 6) % RING]);                               \
        RB = mul2(g2[5], v_[((JJ) + 7) % RING]);                               \
        _Pragma("unroll")                                                      \
        for (int d = 0; d < 5; ++d) {                                          \
            RA = fma2(g2[d], add2(v_[((JJ) + 1 + d) % RING],                   \
                                  v_[((JJ) + 11 - d) % RING]), RA);            \
            RB = fma2(g2[d], add2(v_[((JJ) + 2 + d) % RING],                   \
                                  v_[((JJ) + 12 - d) % RING]), RB);            \
        }                                                                      \
    }
    #define SSIM_EMIT(MP, MM_, EPP, EMM)                                       \
    {                                                                          \
        const u64 a_  = mul2(MP, MP);                                          \
        const u64 b_  = mul2(MM_, MM_);                                        \
        const u64 A_  = mul2(HLF, add2(a_, b_));                               \
        const u64 P2_ = mul2(HLF, add2(a_, neg2(b_)));                         \
        const u64 S_  = mul2(HLF, add2(EPP, EMM));                             \
        const u64 E2_ = mul2(HLF, add2(EPP, neg2(EMM)));                       \
        const u64 n1_ = add2(P2_, C1P);                                        \
        const u64 n2_ = add2(add2(E2_, C2P), neg2(P2_));                       \
        const u64 d1_ = add2(A_, C1P);                                         \
        const u64 d2_ = add2(add2(S_, C2P), neg2(A_));                         \
        const u64 nu_ = mul2(n1_, n2_);                                        \
        const u64 de_ = fma2(d1_, d2_, EPSP);                                  \
        float n0_, n1s_, dd0_, dd1_;                                           \
        upk2(nu_, n0_, n1s_);                                                  \
        upk2(de_, dd0_, dd1_);                                                 \
        float v0_ = __fdividef(n0_,  dd0_);                                    \
        float v1_ = __fdividef(n1s_, dd1_);                                    \
        lsum0 += fminf(fmaxf(v0_, 0.f), 1.f);                                  \
        lsum1 += fminf(fmaxf(v1_, 0.f), 1.f);                                  \
    }
    #define HPAIR(D, PA, MA, PB, MB)                                           \
    {                                                                          \
        hP  = fma2(g2[D], add2(PA, PB), hP);                                   \
        hM  = fma2(g2[D], add2(MA, MB), hM);                                   \
        hPP = fma2(g2[D], fma2(PA, PA, mul2(PB, PB)), hPP);                    \
        hMM = fma2(g2[D], fma2(MA, MA, mul2(MB, MB)), hMM);                    \
    }
    // Stage, hconv, ring write, optional paired emit.  EM: 1 = emit rows.
    #define STEP_CORE(JJ, EM)                                                  \
    {                                                                          \
        float4* buf = &sbuf[wid][(JJ) & 1][0];                                 \
        {                                                                      \
            float4 s1;                                                         \
            s1.x = f1x.x + f1y.x;  s1.y = f1x.y + f1y.y;                       \
            s1.z = f1x.x - f1y.x;  s1.w = f1x.y - f1y.y;                       \
            buf[lane] = s1;                                                    \
            if (lane < NPAIR - 32) {                                           \
                float4 s2;                                                     \
                s2.x = f2x.x + f2y.x;  s2.y = f2x.y + f2y.y;                   \
                s2.z = f2x.x - f2y.x;  s2.w = f2x.y - f2y.y;                   \
                buf[32 + lane] = s2;                                           \
            }                                                                  \
        }                                                                      \
        PREFETCH_NEXT                                                          \
        __syncwarp();                                                          \
        float4 f[7];                                                           \
        _Pragma("unroll")                                                      \
        for (int j = 0; j < 7; ++j) f[j] = buf[lane + j];                      \
        const u64 P0 = pk2(f[0].y, f[1].x), M0 = pk2(f[0].w, f[1].z);          \
        const u64 P1 = pk2(f[1].x, f[1].y), M1 = pk2(f[1].z, f[1].w);          \
        const u64 P2 = pk2(f[1].y, f[2].x), M2 = pk2(f[1].w, f[2].z);          \
        const u64 P3 = pk2(f[2].x, f[2].y), M3 = pk2(f[2].z, f[2].w);          \
        const u64 P4 = pk2(f[2].y, f[3].x), M4 = pk2(f[2].w, f[3].z);          \
        const u64 P5 = pk2(f[3].x, f[3].y), M5 = pk2(f[3].z, f[3].w);          \
        const u64 P6 = pk2(f[3].y, f[4].x), M6 = pk2(f[3].w, f[4].z);          \
        const u64 P7 = pk2(f[4].x, f[4].y), M7 = pk2(f[4].z, f[4].w);          \
        const u64 P8 = pk2(f[4].y, f[5].x), M8 = pk2(f[4].w, f[5].z);          \
        const u64 P9 = pk2(f[5].x, f[5].y), M9 = pk2(f[5].z, f[5].w);          \
        const u64 PA = pk2(f[5].y, f[6].x), MA = pk2(f[5].w, f[6].z);          \
        u64 hP = mul2(g2[5], P5);                                              \
        u64 hM = mul2(g2[5], M5);                                              \
        u64 hPP = mul2(hP, P5);                                                \
        u64 hMM = mul2(hM, M5);                                                \
        HPAIR(0, P0, M0, PA, MA)                                               \
        HPAIR(1, P1, M1, P9, M9)                                               \
        HPAIR(2, P2, M2, P8, M8)                                               \
        HPAIR(3, P3, M3, P7, M7)                                               \
        HPAIR(4, P4, M4, P6, M6)                                               \
        rP[(JJ) % RING] = hP;  rM[(JJ) % RING] = hM;                           \
        myPP[((JJ) % RING) * 32] = hPP;                                        \
        myMM[((JJ) % RING) * 32] = hMM;                                        \
        if (EM) {                                                              \
            u64 mpA, mpB, mmA, mmB, eppA, eppB, emmA, emmB;                    \
            VPAIR_R(mpA, mpB, rP, (JJ))                                        \
            VPAIR_R(mmA, mmB, rM, (JJ))                                        \
            VPAIR_S(eppA, eppB, myPP, (JJ))                                    \
            VPAIR_S(emmA, emmB, myMM, (JJ))                                    \
            SSIM_EMIT(mpA, mmA, eppA, emmA)                                    \
            SSIM_EMIT(mpB, mmB, eppB, emmB)                                    \
        }                                                                      \
    }

    if (r0 >= HALO && r0 + TYO + HALO + 1 <= IMG_H) {
        // ---------------- interior path: no row checks, running pointers ----
        const float* xr = xi + (long)(r0 - HALO) * IMG_W;
        const float* yr = yi + (long)(r0 - HALO) * IMG_W;

        float2 f1x, f1y, f2x, f2y;
        const float2 z = make_float2(0.f, 0.f);
        f1x = c1ok ? __ldg((const float2*)(xr + col1)) : z;
        f1y = c1ok ? __ldg((const float2*)(yr + col1)) : z;
        f2x = c2ok ? __ldg((const float2*)(xr + col2)) : z;
        f2y = c2ok ? __ldg((const float2*)(yr + col2)) : z;
        xr += IMG_W; yr += IMG_W;

        #define PREFETCH_NEXT                                                  \
        {                                                                      \
            f1x = c1ok ? __ldg((const float2*)(xr + col1)) : z;                \
            f1y = c1ok ? __ldg((const float2*)(yr + col1)) : z;                \
            f2x = c2ok ? __ldg((const float2*)(xr + col2)) : z;                \
            f2y = c2ok ? __ldg((const float2*)(yr + col2)) : z;                \
            xr += IMG_W; yr += IMG_W;                                          \
        }

        // Steps 0..11 (emit only at step 11).
        STEP_CORE(0,0)  STEP_CORE(1,0)  STEP_CORE(2,0)  STEP_CORE(3,0)
        STEP_CORE(4,0)  STEP_CORE(5,0)  STEP_CORE(6,0)  STEP_CORE(7,0)
        STEP_CORE(8,0)  STEP_CORE(9,0)  STEP_CORE(10,0) STEP_CORE(11,1)
        // Steps 12..35 (two identical blocks; nothing depends on t).
        #pragma unroll 1
        for (int it = 0; it < 2; ++it) {
            STEP_CORE(0,0)  STEP_CORE(1,1)  STEP_CORE(2,0)  STEP_CORE(3,1)
            STEP_CORE(4,0)  STEP_CORE(5,1)  STEP_CORE(6,0)  STEP_CORE(7,1)
            STEP_CORE(8,0)  STEP_CORE(9,1)  STEP_CORE(10,0) STEP_CORE(11,1)
        }
        // Tail: steps 36..41.
        STEP_CORE(0,0)  STEP_CORE(1,1)  STEP_CORE(2,0)  STEP_CORE(3,1)
        STEP_CORE(4,0)  STEP_CORE(5,1)
        #undef PREFETCH_NEXT
    } else {
        // ---------------- edge path: full row checks ------------------------
        #pragma unroll
        for (int s = 0; s < RING; ++s) { myPP[s * 32] = 0; myMM[s * 32] = 0; }

        float2 f1x, f1y, f2x, f2y;
        {
            const int ir = r0 - HALO;
            const bool rv = (ir >= 0);
            const float* xr = xi + (long)ir * IMG_W;
            const float* yr = yi + (long)ir * IMG_W;
            const float2 z = make_float2(0.f, 0.f);
            f1x = (rv && c1ok) ? __ldg((const float2*)(xr + col1)) : z;
            f1y = (rv && c1ok) ? __ldg((const float2*)(yr + col1)) : z;
            f2x = (rv && c2ok) ? __ldg((const float2*)(xr + col2)) : z;
            f2y = (rv && c2ok) ? __ldg((const float2*)(yr + col2)) : z;
        }

        #define PREFETCH_NEXT                                                  \
        {                                                                      \
            const int irn = r0 - HALO + t + 1;                                 \
            const bool rv = (irn >= 0) && (irn < IMG_H);                       \
            const float* xr = xi + (long)irn * IMG_W;                          \
            const float* yr = yi + (long)irn * IMG_W;                          \
            const float2 z = make_float2(0.f, 0.f);                            \
            f1x = (rv && c1ok) ? __ldg((const float2*)(xr + col1)) : z;        \
            f1y = (rv && c1ok) ? __ldg((const float2*)(yr + col1)) : z;        \
            f2x = (rv && c2ok) ? __ldg((const float2*)(xr + col2)) : z;        \
            f2y = (rv && c2ok) ? __ldg((const float2*)(yr + col2)) : z;        \
        }
        #define STEP_EDGE(JJ)                                                  \
        if (tbase + (JJ) < TLAST) {                                            \
            const int t = tbase + (JJ);                                        \
            STEP_CORE(JJ, (((JJ) & 1) && t >= WIN))                            \
        }

        #pragma unroll 1
        for (int tbase = 0; tbase < NSTEP; tbase += RING) {
            STEP_EDGE(0)  STEP_EDGE(1)  STEP_EDGE(2)  STEP_EDGE(3)
            STEP_EDGE(4)  STEP_EDGE(5)  STEP_EDGE(6)  STEP_EDGE(7)
            STEP_EDGE(8)  STEP_EDGE(9)  STEP_EDGE(10) STEP_EDGE(11)
        }
        #undef STEP_EDGE
        #undef PREFETCH_NEXT
    }

    #undef STEP_CORE
    #undef HPAIR
    #undef SSIM_EMIT
    #undef VPAIR_R
    #undef VPAIR_S

    float ls = lsum0 + lsum1;
    #pragma unroll
    for (int o = 16; o > 0; o >>= 1)
        ls += __shfl_down_sync(0xFFFFFFFFu, ls, o);
    if (lane == 0) swp[wid] = ls;
    __syncthreads();

    if (tid == 0) {
        float bs = swp[0] + swp[1];
        atomicAdd(&g_ssim_acc, (double)bs);
        __threadfence();
        const unsigned nb = gridDim.x * gridDim.y * gridDim.z;
        const unsigned prev = atomicAdd(&g_ssim_cnt, 1u);
        if (prev == nb - 1u) {
            double acc = atomicAdd(&g_ssim_acc, 0.0);
            out[0] = (float)(acc * inv_total);
            g_ssim_acc = 0.0;
            g_ssim_cnt = 0u;
            __threadfence();
        }
    }
}

extern "C" void kernel_launch(void* const* d_in, const int* in_sizes, int n_in,
                              void* d_out, int out_size) {
    const float* x = (const float*)d_in[0];
    const float* y = (const float*)d_in[1];
    const float* w = (const float*)d_in[2];
    float* out = (float*)d_out;

    const long total = (long)in_sizes[0];
    const int nimg = (int)(total / (IMG_H * IMG_W));

    dim3 grid(IMG_W / CBLK, IMG_H / TYO, nimg);
    ssim_main_kernel<<<grid, TPB>>>(x, y, w, out, 1.0 / (double)total);
}

// round 16
// speedup vs baseline: 1.2166x; 1.1004x over previous
#include <cuda_runtime.h>

#define TPB    64     // 2 warps; each warp owns 64 output columns
#define WPC    64
#define CBLK   128
#define TYO    32
#define WIN    11
#define HALO   5
#define IMG_H  512
#define IMG_W  512
#define NSTEP  44     // 4*11 >= TYO+WIN-1 (=42)
#define NPAIR  38

#define C1F  1.0e-4f
#define C2F  9.0e-4f
#define EPSF 1.0e-8f

typedef unsigned long long u64;

__device__ double       g_ssim_acc;
__device__ unsigned int g_ssim_cnt;

__device__ __forceinline__ u64 pk2(float lo, float hi) {
    u64 r; asm("mov.b64 %0,{%1,%2};" : "=l"(r) : "f"(lo), "f"(hi)); return r;
}
__device__ __forceinline__ void upk2(u64 v, float& lo, float& hi) {
    asm("mov.b64 {%0,%1},%2;" : "=f"(lo), "=f"(hi) : "l"(v));
}
__device__ __forceinline__ u64 fma2(u64 a, u64 b, u64 c) {
    u64 d; asm("fma.rn.f32x2 %0,%1,%2,%3;" : "=l"(d) : "l"(a), "l"(b), "l"(c)); return d;
}
__device__ __forceinline__ u64 mul2(u64 a, u64 b) {
    u64 d; asm("mul.rn.f32x2 %0,%1,%2;" : "=l"(d) : "l"(a), "l"(b)); return d;
}
__device__ __forceinline__ u64 add2(u64 a, u64 b) {
    u64 d; asm("add.rn.f32x2 %0,%1,%2;" : "=l"(d) : "l"(a), "l"(b)); return d;
}
__device__ __forceinline__ u64 neg2(u64 a) { return a ^ 0x8000000080000000ull; }

__global__ void __launch_bounds__(TPB, 8) ssim_main_kernel(
    const float* __restrict__ x,
    const float* __restrict__ y,
    const float* __restrict__ w,
    float* __restrict__ out,
    double inv_total)
{
    __shared__ float sg[WIN];
    __shared__ __align__(16) float4 sbuf[2][2][40];      // staging, 2.5KB
    __shared__ u64 ringPP[2][WIN][32];                   // 5.5KB
    __shared__ u64 ringMM[2][WIN][32];                   // 5.5KB
    __shared__ float swp[TPB / 32];

    const int tid  = threadIdx.x;
    const int lane = tid & 31;
    const int wid  = tid >> 5;

    // Separable 1D Gaussian from the 2D window (rows of g g^T sum to g[i]).
    if (tid < WIN) {
        float s = 0.f;
        #pragma unroll
        for (int j = 0; j < WIN; ++j) s += __ldg(w + tid * WIN + j);
        sg[tid] = s;
    }
    __syncthreads();

    u64 g2[6];   // symmetric: tap k uses g2[k<=5 ? k : 10-k]
    #pragma unroll
    for (int d = 0; d < 6; ++d) { float gd = sg[d]; g2[d] = pk2(gd, gd); }

    const u64 C1P  = pk2(C1F, C1F);
    const u64 C2P  = pk2(C2F, C2F);
    const u64 EPSP = pk2(EPSF, EPSF);
    const u64 HLF  = pk2(0.5f, 0.5f);

    const int c0 = blockIdx.x * CBLK;
    const int r0 = blockIdx.y * TYO;
    const long img_off = (long)blockIdx.z * (IMG_H * IMG_W);
    const float* xi = x + img_off;
    const float* yi = y + img_off;

    const int cw = c0 + WPC * wid;
    const int cb = cw - 6;

    const int  col1 = cb + 2 * lane;
    const int  col2 = col1 + 64;
    const bool c1ok = (col1 >= 0) && (col1 < IMG_W);
    const bool c2ok = (lane < NPAIR - 32) && (col2 < IMG_W);

    // rP/rM rings in registers; rPP/rMM rings in SMEM (slot (t % 11)).
    u64 rP[WIN], rM[WIN];
    #pragma unroll
    for (int s = 0; s < WIN; ++s) { rP[s]=0; rM[s]=0; }
    u64* myPP = &ringPP[wid][0][lane];   // stride between slots = 32 u64
    u64* myMM = &ringMM[wid][0][lane];
    #pragma unroll
    for (int s = 0; s < WIN; ++s) { myPP[s * 32] = 0; myMM[s * 32] = 0; }

    float lsum0 = 0.f, lsum1 = 0.f;
    int par = 0;

    // Prefetch row for step 0 (ir = r0-5).
    float2 f1x, f1y, f2x, f2y;
    {
        const int ir = r0 - HALO;
        const bool rv = (ir >= 0);
        const float* xr = xi + (long)ir * IMG_W;
        const float* yr = yi + (long)ir * IMG_W;
        const float2 z = make_float2(0.f, 0.f);
        f1x = (rv && c1ok) ? __ldg((const float2*)(xr + col1)) : z;
        f1y = (rv && c1ok) ? __ldg((const float2*)(yr + col1)) : z;
        f2x = (rv && c2ok) ? __ldg((const float2*)(xr + col2)) : z;
        f2y = (rv && c2ok) ? __ldg((const float2*)(yr + col2)) : z;
    }

    // Vertical conv over a register ring (symmetric pairing, g[d] == g[10-d]).
    #define VPLANE(RES, RNG, JJ)                                               \
    {                                                                          \
        u64 m_ = mul2(g2[5], RNG[((JJ) + 6) % WIN]);                           \
        m_ = fma2(g2[0], add2(RNG[((JJ) + 11) % WIN], RNG[((JJ) + 1) % WIN]), m_); \
        m_ = fma2(g2[1], add2(RNG[((JJ) + 10) % WIN], RNG[((JJ) + 2) % WIN]), m_); \
        m_ = fma2(g2[2], add2(RNG[((JJ) +  9) % WIN], RNG[((JJ) + 3) % WIN]), m_); \
        m_ = fma2(g2[3], add2(RNG[((JJ) +  8) % WIN], RNG[((JJ) + 4) % WIN]), m_); \
        m_ = fma2(g2[4], add2(RNG[((JJ) +  7) % WIN], RNG[((JJ) + 5) % WIN]), m_); \
        RES = m_;                                                              \
    }
    // Vertical conv over a SMEM ring (LDS.64 per slot).
    #define VPLANE_S(RES, BASE, JJ)                                            \
    {                                                                          \
        u64 m_ = mul2(g2[5], (BASE)[(((JJ) + 6) % WIN) * 32]);                 \
        m_ = fma2(g2[0], add2((BASE)[(((JJ) + 11) % WIN) * 32], (BASE)[(((JJ) + 1) % WIN) * 32]), m_); \
        m_ = fma2(g2[1], add2((BASE)[(((JJ) + 10) % WIN) * 32], (BASE)[(((JJ) + 2) % WIN) * 32]), m_); \
        m_ = fma2(g2[2], add2((BASE)[(((JJ) +  9) % WIN) * 32], (BASE)[(((JJ) + 3) % WIN) * 32]), m_); \
        m_ = fma2(g2[3], add2((BASE)[(((JJ) +  8) % WIN) * 32], (BASE)[(((JJ) + 4) % WIN) * 32]), m_); \
        m_ = fma2(g2[4], add2((BASE)[(((JJ) +  7) % WIN) * 32], (BASE)[(((JJ) + 5) % WIN) * 32]), m_); \
        RES = m_;                                                              \
    }

    // Symmetric horizontal tap pair (g[d] == g[10-d]).
    #define HPAIR(D, PA, MA, PB, MB)                                           \
    {                                                                          \
        hP  = fma2(g2[D], add2(PA, PB), hP);                                   \
        hM  = fma2(g2[D], add2(MA, MB), hM);                                   \
        hPP = fma2(g2[D], fma2(PA, PA, mul2(PB, PB)), hPP);                    \
        hMM = fma2(g2[D], fma2(MA, MA, mul2(MB, MB)), hMM);                    \
    }

    #define SSIM_STEP(JJ)                                                      \
    if (tbase + (JJ) < TYO + WIN - 1) {                                        \
        const int t = tbase + (JJ);                                            \
        float4* buf = &sbuf[wid][par][0];                                      \
        /* Stage prefetched row as interleaved (p0,p1,m0,m1) pairs. */         \
        {                                                                      \
            float4 s1;                                                         \
            s1.x = f1x.x + f1y.x;  s1.y = f1x.y + f1y.y;                       \
            s1.z = f1x.x - f1y.x;  s1.w = f1x.y - f1y.y;                       \
            buf[lane] = s1;                                                    \
            if (lane < NPAIR - 32) {                                           \
                float4 s2;                                                     \
                s2.x = f2x.x + f2y.x;  s2.y = f2x.y + f2y.y;                   \
                s2.z = f2x.x - f2y.x;  s2.w = f2x.y - f2y.y;                   \
                buf[32 + lane] = s2;                                           \
            }                                                                  \
        }                                                                      \
        /* Prefetch next row. */                                               \
        {                                                                      \
            const int irn = r0 - HALO + t + 1;                                 \
            const bool rv = (irn >= 0) && (irn < IMG_H);                       \
            const float* xr = xi + (long)irn * IMG_W;                          \
            const float* yr = yi + (long)irn * IMG_W;                          \
            const float2 z = make_float2(0.f, 0.f);                            \
            f1x = (rv && c1ok) ? __ldg((const float2*)(xr + col1)) : z;        \
            f1y = (rv && c1ok) ? __ldg((const float2*)(yr + col1)) : z;        \
            f2x = (rv && c2ok) ? __ldg((const float2*)(xr + col2)) : z;        \
            f2y = (rv && c2ok) ? __ldg((const float2*)(yr + col2)) : z;        \
        }                                                                      \
        __syncwarp();                                                          \
        /* Window pairs: 7 LDS.128. */                                         \
        float4 f[7];                                                           \
        _Pragma("unroll")                                                      \
        for (int j = 0; j < 7; ++j) f[j] = buf[lane + j];                      \
        /* 11 window packs per plane. */                                       \
        const u64 P0 = pk2(f[0].y, f[1].x), M0 = pk2(f[0].w, f[1].z);          \
        const u64 P1 = pk2(f[1].x, f[1].y), M1 = pk2(f[1].z, f[1].w);          \
        const u64 P2 = pk2(f[1].y, f[2].x), M2 = pk2(f[1].w, f[2].z);          \
        const u64 P3 = pk2(f[2].x, f[2].y), M3 = pk2(f[2].z, f[2].w);          \
        const u64 P4 = pk2(f[2].y, f[3].x), M4 = pk2(f[2].w, f[3].z);          \
        const u64 P5 = pk2(f[3].x, f[3].y), M5 = pk2(f[3].z, f[3].w);          \
        const u64 P6 = pk2(f[3].y, f[4].x), M6 = pk2(f[3].w, f[4].z);          \
        const u64 P7 = pk2(f[4].x, f[4].y), M7 = pk2(f[4].z, f[4].w);          \
        const u64 P8 = pk2(f[4].y, f[5].x), M8 = pk2(f[4].w, f[5].z);          \
        const u64 P9 = pk2(f[5].x, f[5].y), M9 = pk2(f[5].z, f[5].w);          \
        const u64 PA = pk2(f[5].y, f[6].x), MA = pk2(f[5].w, f[6].z);          \
        /* Center tap, then symmetric pairs (54 packed ops vs 66). */          \
        u64 hP = mul2(g2[5], P5);                                              \
        u64 hM = mul2(g2[5], M5);                                              \
        u64 hPP = mul2(hP, P5);                                                \
        u64 hMM = mul2(hM, M5);                                                \
        HPAIR(0, P0, M0, PA, MA)                                               \
        HPAIR(1, P1, M1, P9, M9)                                               \
        HPAIR(2, P2, M2, P8, M8)                                               \
        HPAIR(3, P3, M3, P7, M7)                                               \
        HPAIR(4, P4, M4, P6, M6)                                               \
        rP[(JJ)] = hP;  rM[(JJ)] = hM;                                         \
        myPP[(JJ) * 32] = hPP;                                                 \
        myMM[(JJ) * 32] = hMM;                                                 \
        /* Emit output row r0 + t - 10. */                                     \
        if (t >= WIN - 1) {                                                    \
            u64 mp, mm, epp, emm;                                              \
            VPLANE(mp, rP, (JJ))                                               \
            VPLANE(mm, rM, (JJ))                                               \
            VPLANE_S(epp, myPP, (JJ))                                          \
            VPLANE_S(emm, myMM, (JJ))                                          \
            const u64 a   = mul2(mp, mp);                                      \
            const u64 b   = mul2(mm, mm);                                      \
            const u64 A    = mul2(HLF, add2(a, b));        /* mu_x^2+mu_y^2 */ \
            const u64 P2_  = mul2(HLF, add2(a, neg2(b)));  /* 2*mu_x*mu_y  */  \
            const u64 S    = mul2(HLF, add2(epp, emm));    /* E[x^2]+E[y^2] */ \
            const u64 E2   = mul2(HLF, add2(epp, neg2(emm))); /* 2*E[xy]   */  \
            const u64 n1   = add2(P2_, C1P);                                   \
            const u64 n2   = add2(add2(E2, C2P), neg2(P2_));                   \
            const u64 d1   = add2(A, C1P);                                     \
            const u64 d2   = add2(add2(S, C2P), neg2(A));                      \
            const u64 num  = mul2(n1, n2);                                     \
            const u64 den  = fma2(d1, d2, EPSP);                               \
            float n0, n1s, dd0, dd1;                                           \
            upk2(num, n0, n1s);                                                \
            upk2(den, dd0, dd1);                                               \
            float v0 = __fdividef(n0,  dd0);                                   \
            float v1 = __fdividef(n1s, dd1);                                   \
            v0 = fminf(fmaxf(v0, 0.f), 1.f);                                   \
            v1 = fminf(fmaxf(v1, 0.f), 1.f);                                   \
            lsum0 += v0;                                                       \
            lsum1 += v1;                                                       \
        }                                                                      \
        par ^= 1;                                                              \
    }

    #pragma unroll 1
    for (int tbase = 0; tbase < NSTEP; tbase += WIN) {
        SSIM_STEP(0)  SSIM_STEP(1)  SSIM_STEP(2)  SSIM_STEP(3)
        SSIM_STEP(4)  SSIM_STEP(5)  SSIM_STEP(6)  SSIM_STEP(7)
        SSIM_STEP(8)  SSIM_STEP(9)  SSIM_STEP(10)
    }
    #undef SSIM_STEP
    #undef HPAIR
    #undef VPLANE
    #undef VPLANE_S

    // Block reduction.
    float ls = lsum0 + lsum1;
    #pragma unroll
    for (int o = 16; o > 0; o >>= 1)
        ls += __shfl_down_sync(0xFFFFFFFFu, ls, o);
    if (lane == 0) swp[wid] = ls;
    __syncthreads();

    if (tid == 0) {
        float bs = swp[0] + swp[1];
        atomicAdd(&g_ssim_acc, (double)bs);
        __threadfence();
        const unsigned nb = gridDim.x * gridDim.y * gridDim.z;
        const unsigned prev = atomicAdd(&g_ssim_cnt, 1u);
        if (prev == nb - 1u) {
            double acc = atomicAdd(&g_ssim_acc, 0.0);
            out[0] = (float)(acc * inv_total);
            g_ssim_acc = 0.0;
            g_ssim_cnt = 0u;
            __threadfence();
        }
    }
}

extern "C" void kernel_launch(void* const* d_in, const int* in_sizes, int n_in,
                              void* d_out, int out_size) {
    const float* x = (const float*)d_in[0];
    const float* y = (const float*)d_in[1];
    const float* w = (const float*)d_in[2];
    float* out = (float*)d_out;

    const long total = (long)in_sizes[0];
    const int nimg = (int)(total / (IMG_H * IMG_W));

    dim3 grid(IMG_W / CBLK, IMG_H / TYO, nimg);
    ssim_main_kernel<<<grid, TPB>>>(x, y, w, out, 1.0 / (double)total);
}

// round 17
// speedup vs baseline: 1.3720x; 1.1278x over previous
#include <cuda_runtime.h>

#define TPB    64     // 2 warps; each warp owns 64 output columns
#define WPC    64
#define CBLK   128
#define TYO    32
#define WIN    11
#define HALO   5
#define RING   12     // 12-slot ring enables paired-row emit
#define IMG_H  512
#define IMG_W  512
#define TLAST  42     // steps t = 0..41
#define NSTEP  48     // 4 * RING
#define NPAIR  38

#define C1F  1.0e-4f
#define C2F  9.0e-4f
#define EPSF 1.0e-8f

typedef unsigned long long u64;

__device__ double       g_ssim_acc;
__device__ unsigned int g_ssim_cnt;

__device__ __forceinline__ u64 pk2(float lo, float hi) {
    u64 r; asm("mov.b64 %0,{%1,%2};" : "=l"(r) : "f"(lo), "f"(hi)); return r;
}
__device__ __forceinline__ void upk2(u64 v, float& lo, float& hi) {
    asm("mov.b64 {%0,%1},%2;" : "=f"(lo), "=f"(hi) : "l"(v));
}
__device__ __forceinline__ u64 fma2(u64 a, u64 b, u64 c) {
    u64 d; asm("fma.rn.f32x2 %0,%1,%2,%3;" : "=l"(d) : "l"(a), "l"(b), "l"(c)); return d;
}
__device__ __forceinline__ u64 mul2(u64 a, u64 b) {
    u64 d; asm("mul.rn.f32x2 %0,%1,%2;" : "=l"(d) : "l"(a), "l"(b)); return d;
}
__device__ __forceinline__ u64 add2(u64 a, u64 b) {
    u64 d; asm("add.rn.f32x2 %0,%1,%2;" : "=l"(d) : "l"(a), "l"(b)); return d;
}
__device__ __forceinline__ u64 neg2(u64 a) { return a ^ 0x8000000080000000ull; }

__global__ void __launch_bounds__(TPB, 8) ssim_main_kernel(
    const float* __restrict__ x,
    const float* __restrict__ y,
    const float* __restrict__ w,
    float* __restrict__ out,
    double inv_total)
{
    __shared__ float sg[WIN];
    __shared__ __align__(16) float4 sbuf[2][2][40];      // staging, 2.5KB
    __shared__ u64 ringPP[2][RING][32];                  // 6KB
    __shared__ u64 ringMM[2][RING][32];                  // 6KB
    __shared__ float swp[TPB / 32];

    const int tid  = threadIdx.x;
    const int lane = tid & 31;
    const int wid  = tid >> 5;

    // Separable 1D Gaussian from the 2D window (rows of g g^T sum to g[i]).
    if (tid < WIN) {
        float s = 0.f;
        #pragma unroll
        for (int j = 0; j < WIN; ++j) s += __ldg(w + tid * WIN + j);
        sg[tid] = s;
    }
    __syncthreads();

    u64 g2[6];   // symmetric: tap k uses g2[k<=5 ? k : 10-k]
    #pragma unroll
    for (int d = 0; d < 6; ++d) { float gd = sg[d]; g2[d] = pk2(gd, gd); }

    const u64 C1P  = pk2(C1F, C1F);
    const u64 C2P  = pk2(C2F, C2F);
    const u64 EPSP = pk2(EPSF, EPSF);
    const u64 HLF  = pk2(0.5f, 0.5f);

    const int c0 = blockIdx.x * CBLK;
    const int r0 = blockIdx.y * TYO;
    const long img_off = (long)blockIdx.z * (IMG_H * IMG_W);
    const float* xi = x + img_off;
    const float* yi = y + img_off;

    const int cw = c0 + WPC * wid;
    const int cb = cw - 6;

    const int  col1 = cb + 2 * lane;
    const int  col2 = col1 + 64;
    const bool c1ok = (col1 >= 0) && (col1 < IMG_W);
    const bool c2ok = (lane < NPAIR - 32) && (col2 < IMG_W);

    // rP/rM rings in registers (12 slots); rPP/rMM rings in SMEM.
    u64 rP[RING], rM[RING];
    #pragma unroll
    for (int s = 0; s < RING; ++s) { rP[s]=0; rM[s]=0; }
    u64* myPP = &ringPP[wid][0][lane];   // slot stride = 32 u64
    u64* myMM = &ringMM[wid][0][lane];

    float lsum0 = 0.f, lsum1 = 0.f;
    int par = 0;

    // Prefetch row for step 0 (ir = r0-5).
    float2 f1x, f1y, f2x, f2y;
    {
        const int ir = r0 - HALO;
        const bool rv = (ir >= 0);
        const float* xr = xi + (long)ir * IMG_W;
        const float* yr = yi + (long)ir * IMG_W;
        const float2 z = make_float2(0.f, 0.f);
        f1x = (rv && c1ok) ? __ldg((const float2*)(xr + col1)) : z;
        f1y = (rv && c1ok) ? __ldg((const float2*)(yr + col1)) : z;
        f2x = (rv && c2ok) ? __ldg((const float2*)(xr + col2)) : z;
        f2y = (rv && c2ok) ? __ldg((const float2*)(yr + col2)) : z;
    }

    // Paired-row vertical conv from a register ring.
    // Row A = t-11 reads slots (JJ+1+d)%12, row B = t-10 reads (JJ+2+d)%12.
    #define VPAIR_R(RA, RB, RNG, JJ)                                           \
    {                                                                          \
        RA = mul2(g2[5], RNG[((JJ) + 6) % RING]);                              \
        RB = mul2(g2[5], RNG[((JJ) + 7) % RING]);                              \
        _Pragma("unroll")                                                      \
        for (int d = 0; d < 5; ++d) {                                          \
            RA = fma2(g2[d], add2(RNG[((JJ) + 1 + d) % RING],                  \
                                  RNG[((JJ) + 11 - d) % RING]), RA);           \
            RB = fma2(g2[d], add2(RNG[((JJ) + 2 + d) % RING],                  \
                                  RNG[((JJ) + 12 - d) % RING]), RB);           \
        }                                                                      \
    }
    // Same from a SMEM ring: each slot read exactly once per emit pair.
    #define VPAIR_S(RA, RB, BASE, JJ)                                          \
    {                                                                          \
        u64 v_[RING];                                                          \
        _Pragma("unroll")                                                      \
        for (int s = 0; s < RING; ++s) v_[s] = (BASE)[s * 32];                 \
        RA = mul2(g2[5], v_[((JJ) + 6) % RING]);                               \
        RB = mul2(g2[5], v_[((JJ) + 7) % RING]);                               \
        _Pragma("unroll")                                                      \
        for (int d = 0; d < 5; ++d) {                                          \
            RA = fma2(g2[d], add2(v_[((JJ) + 1 + d) % RING],                   \
                                  v_[((JJ) + 11 - d) % RING]), RA);            \
            RB = fma2(g2[d], add2(v_[((JJ) + 2 + d) % RING],                   \
                                  v_[((JJ) + 12 - d) % RING]), RB);            \
        }                                                                      \
    }
    // SSIM rational for one packed output pair; adds into lsum0/lsum1.
    #define SSIM_EMIT(MP, MM_, EPP, EMM)                                       \
    {                                                                          \
        const u64 a_  = mul2(MP, MP);                                          \
        const u64 b_  = mul2(MM_, MM_);                                        \
        const u64 A_  = mul2(HLF, add2(a_, b_));                               \
        const u64 P2_ = mul2(HLF, add2(a_, neg2(b_)));                         \
        const u64 S_  = mul2(HLF, add2(EPP, EMM));                             \
        const u64 E2_ = mul2(HLF, add2(EPP, neg2(EMM)));                       \
        const u64 n1_ = add2(P2_, C1P);                                        \
        const u64 n2_ = add2(add2(E2_, C2P), neg2(P2_));                       \
        const u64 d1_ = add2(A_, C1P);                                         \
        const u64 d2_ = add2(add2(S_, C2P), neg2(A_));                         \
        const u64 nu_ = mul2(n1_, n2_);                                        \
        const u64 de_ = fma2(d1_, d2_, EPSP);                                  \
        float n0_, n1s_, dd0_, dd1_;                                           \
        upk2(nu_, n0_, n1s_);                                                  \
        upk2(de_, dd0_, dd1_);                                                 \
        float v0_ = __fdividef(n0_,  dd0_);                                    \
        float v1_ = __fdividef(n1s_, dd1_);                                    \
        lsum0 += fminf(fmaxf(v0_, 0.f), 1.f);                                  \
        lsum1 += fminf(fmaxf(v1_, 0.f), 1.f);                                  \
    }
    // Round-6 lazy tap: packs formed per tap, consumed immediately.
    #define TAP(PP, PM, GK)                                                    \
    {                                                                          \
        const u64 gp_ = mul2(GK, PP);                                          \
        const u64 gm_ = mul2(GK, PM);                                          \
        hP  = add2(hP,  gp_);                                                  \
        hM  = add2(hM,  gm_);                                                  \
        hPP = fma2(gp_, PP, hPP);                                              \
        hMM = fma2(gm_, PM, hMM);                                              \
    }

    #define SSIM_STEP(JJ)                                                      \
    if (tbase + (JJ) < TLAST) {                                                \
        const int t = tbase + (JJ);                                            \
        float4* buf = &sbuf[wid][par][0];                                      \
        /* Stage prefetched row as interleaved (p0,p1,m0,m1) pairs. */         \
        {                                                                      \
            float4 s1;                                                         \
            s1.x = f1x.x + f1y.x;  s1.y = f1x.y + f1y.y;                       \
            s1.z = f1x.x - f1y.x;  s1.w = f1x.y - f1y.y;                       \
            buf[lane] = s1;                                                    \
            if (lane < NPAIR - 32) {                                           \
                float4 s2;                                                     \
                s2.x = f2x.x + f2y.x;  s2.y = f2x.y + f2y.y;                   \
                s2.z = f2x.x - f2y.x;  s2.w = f2x.y - f2y.y;                   \
                buf[32 + lane] = s2;                                           \
            }                                                                  \
        }                                                                      \
        /* Prefetch next row. */                                               \
        {                                                                      \
            const int irn = r0 - HALO + t + 1;                                 \
            const bool rv = (irn >= 0) && (irn < IMG_H);                       \
            const float* xr = xi + (long)irn * IMG_W;                          \
            const float* yr = yi + (long)irn * IMG_W;                          \
            const float2 z = make_float2(0.f, 0.f);                            \
            f1x = (rv && c1ok) ? __ldg((const float2*)(xr + col1)) : z;        \
            f1y = (rv && c1ok) ? __ldg((const float2*)(yr + col1)) : z;        \
            f2x = (rv && c2ok) ? __ldg((const float2*)(xr + col2)) : z;        \
            f2y = (rv && c2ok) ? __ldg((const float2*)(yr + col2)) : z;        \
        }                                                                      \
        __syncwarp();                                                          \
        /* Window pairs: 7 LDS.128. */                                         \
        float4 f[7];                                                           \
        _Pragma("unroll")                                                      \
        for (int j = 0; j < 7; ++j) f[j] = buf[lane + j];                      \
        /* Horizontal conv: 11 lazy taps over (p, m) and squares. */           \
        u64 hP, hM, hPP, hMM;                                                  \
        {   /* k = 0 (cross pack) */                                           \
            const u64 Pp = pk2(f[0].y, f[1].x);                                \
            const u64 Pm = pk2(f[0].w, f[1].z);                                \
            const u64 gp_ = mul2(g2[0], Pp);                                   \
            const u64 gm_ = mul2(g2[0], Pm);                                   \
            hP = gp_; hM = gm_;                                                \
            hPP = mul2(gp_, Pp);                                               \
            hMM = mul2(gm_, Pm);                                               \
        }                                                                      \
        { const u64 Pp = pk2(f[1].x, f[1].y), Pm = pk2(f[1].z, f[1].w); TAP(Pp, Pm, g2[1]) }  /* k=1  */ \
        { const u64 Pp = pk2(f[1].y, f[2].x), Pm = pk2(f[1].w, f[2].z); TAP(Pp, Pm, g2[2]) }  /* k=2  */ \
        { const u64 Pp = pk2(f[2].x, f[2].y), Pm = pk2(f[2].z, f[2].w); TAP(Pp, Pm, g2[3]) }  /* k=3  */ \
        { const u64 Pp = pk2(f[2].y, f[3].x), Pm = pk2(f[2].w, f[3].z); TAP(Pp, Pm, g2[4]) }  /* k=4  */ \
        { const u64 Pp = pk2(f[3].x, f[3].y), Pm = pk2(f[3].z, f[3].w); TAP(Pp, Pm, g2[5]) }  /* k=5  */ \
        { const u64 Pp = pk2(f[3].y, f[4].x), Pm = pk2(f[3].w, f[4].z); TAP(Pp, Pm, g2[4]) }  /* k=6  */ \
        { const u64 Pp = pk2(f[4].x, f[4].y), Pm = pk2(f[4].z, f[4].w); TAP(Pp, Pm, g2[3]) }  /* k=7  */ \
        { const u64 Pp = pk2(f[4].y, f[5].x), Pm = pk2(f[4].w, f[5].z); TAP(Pp, Pm, g2[2]) }  /* k=8  */ \
        { const u64 Pp = pk2(f[5].x, f[5].y), Pm = pk2(f[5].z, f[5].w); TAP(Pp, Pm, g2[1]) }  /* k=9  */ \
        { const u64 Pp = pk2(f[5].y, f[6].x), Pm = pk2(f[5].w, f[6].z); TAP(Pp, Pm, g2[0]) }  /* k=10 */ \
        rP[(JJ) % RING] = hP;  rM[(JJ) % RING] = hM;                           \
        myPP[((JJ) % RING) * 32] = hPP;                                        \
        myMM[((JJ) % RING) * 32] = hMM;                                        \
        /* Paired emit: rows t-11 and t-10 at odd t >= 11. */                  \
        if (((JJ) & 1) && t >= WIN) {                                          \
            u64 mpA, mpB, mmA, mmB, eppA, eppB, emmA, emmB;                    \
            VPAIR_R(mpA, mpB, rP, (JJ))                                        \
            VPAIR_R(mmA, mmB, rM, (JJ))                                        \
            VPAIR_S(eppA, eppB, myPP, (JJ))                                    \
            VPAIR_S(emmA, emmB, myMM, (JJ))                                    \
            SSIM_EMIT(mpA, mmA, eppA, emmA)                                    \
            SSIM_EMIT(mpB, mmB, eppB, emmB)                                    \
        }                                                                      \
        par ^= 1;                                                              \
    }

    #pragma unroll 1
    for (int tbase = 0; tbase < NSTEP; tbase += RING) {
        SSIM_STEP(0)  SSIM_STEP(1)  SSIM_STEP(2)  SSIM_STEP(3)
        SSIM_STEP(4)  SSIM_STEP(5)  SSIM_STEP(6)  SSIM_STEP(7)
        SSIM_STEP(8)  SSIM_STEP(9)  SSIM_STEP(10) SSIM_STEP(11)
    }
    #undef SSIM_STEP
    #undef TAP
    #undef SSIM_EMIT
    #undef VPAIR_R
    #undef VPAIR_S

    // Block reduction.
    float ls = lsum0 + lsum1;
    #pragma unroll
    for (int o = 16; o > 0; o >>= 1)
        ls += __shfl_down_sync(0xFFFFFFFFu, ls, o);
    if (lane == 0) swp[wid] = ls;
    __syncthreads();

    if (tid == 0) {
        float bs = swp[0] + swp[1];
        atomicAdd(&g_ssim_acc, (double)bs);
        __threadfence();
        const unsigned nb = gridDim.x * gridDim.y * gridDim.z;
        const unsigned prev = atomicAdd(&g_ssim_cnt, 1u);
        if (prev == nb - 1u) {
            double acc = atomicAdd(&g_ssim_acc, 0.0);
            out[0] = (float)(acc * inv_total);
            g_ssim_acc = 0.0;
            g_ssim_cnt = 0u;
            __threadfence();
        }
    }
}

extern "C" void kernel_launch(void* const* d_in, const int* in_sizes, int n_in,
                              void* d_out, int out_size) {
    const float* x = (const float*)d_in[0];
    const float* y = (const float*)d_in[1];
    const float* w = (const float*)d_in[2];
    float* out = (float*)d_out;

    const long total = (long)in_sizes[0];
    const int nimg = (int)(total / (IMG_H * IMG_W));

    dim3 grid(IMG_W / CBLK, IMG_H / TYO, nimg);
    ssim_main_kernel<<<grid, TPB>>>(x, y, w, out, 1.0 / (double)total);
}